// round 13
// baseline (speedup 1.0000x reference)
#include <cuda_runtime.h>
#include <cuda_bf16.h>
#include <cstdint>

// Problem constants
#define BATCH 2
#define S_LEN 2048
#define EMB   1024
#define NH    16
#define HD    64
#define QKV_N (3 * EMB)        // 3072
#define ROWS  (BATCH * S_LEN)  // 4096
#define GK    EMB              // GEMM K = 1024 for both GEMMs

// ---------------------------------------------------------------------------
// Scratch (device globals — allocation-free)
// ---------------------------------------------------------------------------
__device__ __align__(256) __nv_bfloat16 g_qkvh[ (size_t)ROWS * QKV_N ]; // QKV hi
__device__ __align__(256) __nv_bfloat16 g_qkvl[ (size_t)ROWS * QKV_N ]; // QKV lo
__device__ __align__(256) __nv_bfloat16 g_ath [ (size_t)ROWS * EMB ];   // attn hi
__device__ __align__(256) __nv_bfloat16 g_atl [ (size_t)ROWS * EMB ];   // attn lo
__device__ __align__(256) __nv_bfloat16 g_xh  [ (size_t)ROWS * EMB ];
__device__ __align__(256) __nv_bfloat16 g_xl  [ (size_t)ROWS * EMB ];
// transposed weight splits: [N, K] K-major
__device__ __align__(256) __nv_bfloat16 g_wqh[ (size_t)QKV_N * EMB ];
__device__ __align__(256) __nv_bfloat16 g_wql[ (size_t)QKV_N * EMB ];
__device__ __align__(256) __nv_bfloat16 g_wph[ (size_t)EMB * EMB ];
__device__ __align__(256) __nv_bfloat16 g_wpl[ (size_t)EMB * EMB ];

// ---------------------------------------------------------------------------
// helpers (non-arch-gated PTX only: cp.async / ldmatrix / mma.sync)
// ---------------------------------------------------------------------------
__device__ __forceinline__ uint32_t smem_u32(const void* p) {
    uint32_t a;
    asm("{ .reg .u64 t; cvta.to.shared.u64 t, %1; cvt.u32.u64 %0, t; }"
        : "=r"(a) : "l"(p));
    return a;
}

#define CP_ASYNC16(dst, src) \
    asm volatile("cp.async.cg.shared.global [%0], [%1], 16;" :: "r"(dst), "l"(src))
#define CP_COMMIT() asm volatile("cp.async.commit_group;" ::: "memory")
#define CP_WAIT(n)  asm volatile("cp.async.wait_group %0;" :: "n"(n) : "memory")

#define LDMATRIX_X4(r0, r1, r2, r3, addr) \
    asm volatile("ldmatrix.sync.aligned.m8n8.x4.shared.b16 {%0,%1,%2,%3}, [%4];" \
                 : "=r"(r0), "=r"(r1), "=r"(r2), "=r"(r3) : "r"(addr))

#define LDMATRIX_X4_T(r0, r1, r2, r3, addr) \
    asm volatile("ldmatrix.sync.aligned.m8n8.x4.trans.shared.b16 {%0,%1,%2,%3}, [%4];" \
                 : "=r"(r0), "=r"(r1), "=r"(r2), "=r"(r3) : "r"(addr))

#define MMA16816(c0, c1, c2, c3, a0, a1, a2, a3, b0, b1)                        \
    asm volatile("mma.sync.aligned.m16n8k16.row.col.f32.bf16.bf16.f32 "         \
                 "{%0,%1,%2,%3}, {%4,%5,%6,%7}, {%8,%9}, {%0,%1,%2,%3};"        \
                 : "+f"(c0), "+f"(c1), "+f"(c2), "+f"(c3)                       \
                 : "r"(a0), "r"(a1), "r"(a2), "r"(a3), "r"(b0), "r"(b1))

__device__ __forceinline__ uint32_t bf2u(__nv_bfloat162 v) {
    return *reinterpret_cast<uint32_t*>(&v);
}

// ---------------------------------------------------------------------------
// fp32 -> bf16 hi/lo split (elementwise, float4 vectorized)
// ---------------------------------------------------------------------------
__global__ void split_kernel(const float* __restrict__ in,
                             __nv_bfloat16* __restrict__ hi,
                             __nv_bfloat16* __restrict__ lo, int n4)
{
    int i = blockIdx.x * blockDim.x + threadIdx.x;
    if (i >= n4) return;
    float4 v = ((const float4*)in)[i];
    __nv_bfloat16 h0 = __float2bfloat16(v.x);
    __nv_bfloat16 h1 = __float2bfloat16(v.y);
    __nv_bfloat16 h2 = __float2bfloat16(v.z);
    __nv_bfloat16 h3 = __float2bfloat16(v.w);
    __nv_bfloat16 l0 = __float2bfloat16(v.x - __bfloat162float(h0));
    __nv_bfloat16 l1 = __float2bfloat16(v.y - __bfloat162float(h1));
    __nv_bfloat16 l2 = __float2bfloat16(v.z - __bfloat162float(h2));
    __nv_bfloat16 l3 = __float2bfloat16(v.w - __bfloat162float(h3));
    __nv_bfloat162 ph0; ph0.x = h0; ph0.y = h1;
    __nv_bfloat162 ph1; ph1.x = h2; ph1.y = h3;
    __nv_bfloat162 pl0; pl0.x = l0; pl0.y = l1;
    __nv_bfloat162 pl1; pl1.x = l2; pl1.y = l3;
    ((__nv_bfloat162*)hi)[2 * i]     = ph0;
    ((__nv_bfloat162*)hi)[2 * i + 1] = ph1;
    ((__nv_bfloat162*)lo)[2 * i]     = pl0;
    ((__nv_bfloat162*)lo)[2 * i + 1] = pl1;
}

// ---------------------------------------------------------------------------
// Weight transpose + split: W[K,N] fp32 -> Th/Tl[N,K] bf16
// ---------------------------------------------------------------------------
__global__ void wsplit_kernel(const float* __restrict__ W,
                              __nv_bfloat16* __restrict__ Th,
                              __nv_bfloat16* __restrict__ Tl, int K, int N)
{
    __shared__ float t[32][33];
    int tx = threadIdx.x, ty = threadIdx.y;
    int n0 = blockIdx.x * 32, k0 = blockIdx.y * 32;
    for (int j = ty; j < 32; j += 8)
        t[j][tx] = W[(size_t)(k0 + j) * N + n0 + tx];
    __syncthreads();
    for (int j = ty; j < 32; j += 8) {
        float v = t[tx][j];
        __nv_bfloat16 h = __float2bfloat16(v);
        __nv_bfloat16 l = __float2bfloat16(v - __bfloat162float(h));
        size_t o = (size_t)(n0 + j) * K + k0 + tx;
        Th[o] = h;
        Tl[o] = l;
    }
}

// ---------------------------------------------------------------------------
// bf16x3 GEMM via mma.sync: C = A@Bt^T + bias.
// 4-stage cp.async pipeline, one __syncthreads per stage.
// MMA loop is TERM-MAJOR: same-accumulator reuse distance = 16 (hides HMMA lat).
// Epilogue: if Ch != null, write bf16 hi/lo split; else fp32 C.
// ---------------------------------------------------------------------------
#define BK 32
#define NSTAGE (GK / BK)   // 32
#define STG_BYTES 32768
#define NPIPE 4

__global__ __launch_bounds__(256, 1)
void gemm_mma_kernel(const __nv_bfloat16* __restrict__ Ah,
                     const __nv_bfloat16* __restrict__ Al,
                     const __nv_bfloat16* __restrict__ Bh,
                     const __nv_bfloat16* __restrict__ Bl,
                     const float* __restrict__ bias,
                     float* __restrict__ C,
                     __nv_bfloat16* __restrict__ Ch,
                     __nv_bfloat16* __restrict__ Cl, int N)
{
    extern __shared__ char smc[];
    const uint32_t sbase = smem_u32(smc);
    const int tid  = threadIdx.x;
    const int wid  = tid >> 5;
    const int lane = tid & 31;
    const int bn = blockIdx.x, bm = blockIdx.y;
    const int wm = wid >> 1;
    const int wn = wid & 1;

    const __nv_bfloat16* gT[4] = {
        Ah + (size_t)bm * 128 * GK, Al + (size_t)bm * 128 * GK,
        Bh + (size_t)bn * 128 * GK, Bl + (size_t)bn * 128 * GK };

    auto stage_load = [&](int c) {
        const int s = c % NPIPE;
        const int k0 = c * BK;
#pragma unroll
        for (int t = 0; t < 4; t++) {
            const __nv_bfloat16* g = gT[t];
            const uint32_t sb = sbase + s * STG_BYTES + t * 8192;
#pragma unroll
            for (int r2 = 0; r2 < 2; r2++) {
                int idx = tid + r2 * 256;
                int row = idx >> 2;
                int ch  = idx & 3;
                int sw  = ch ^ ((row >> 1) & 3);
                const char* src = (const char*)(g + (size_t)row * GK + k0) + ch * 16;
                CP_ASYNC16(sb + row * 64 + sw * 16, src);
            }
        }
        CP_COMMIT();
    };

    float acc[2][8][4];
#pragma unroll
    for (int i = 0; i < 2; i++)
#pragma unroll
        for (int j = 0; j < 8; j++)
#pragma unroll
            for (int q = 0; q < 4; q++) acc[i][j][q] = 0.f;

    // prologue: stages 0..2 in flight; wait for stage 0
    stage_load(0);
    stage_load(1);
    stage_load(2);
    CP_WAIT(2);
    __syncthreads();

    for (int c = 0; c < NSTAGE; c++) {
        // issue load for stage c+3 (its slot was last read in iter c-1,
        // protected by that iteration's trailing barrier)
        if (c + 3 < NSTAGE) stage_load(c + 3);

        const uint32_t st = sbase + (uint32_t)(c % NPIPE) * STG_BYTES;
        const uint32_t sA[2] = { st, st + 8192 };
        const uint32_t sB[2] = { st + 16384, st + 24576 };

#pragma unroll
        for (int kk = 0; kk < 2; kk++) {
            uint32_t a[2][2][4];
#pragma unroll
            for (int hl = 0; hl < 2; hl++)
#pragma unroll
                for (int mf = 0; mf < 2; mf++) {
                    int row = wm * 32 + mf * 16 + (lane & 7) + ((lane >> 3) & 1) * 8;
                    int ch  = kk * 2 + (lane >> 4);
                    int sw  = ch ^ ((row >> 1) & 3);
                    uint32_t addr = sA[hl] + row * 64 + sw * 16;
                    LDMATRIX_X4(a[hl][mf][0], a[hl][mf][1], a[hl][mf][2], a[hl][mf][3], addr);
                }
            uint32_t b[2][4][4];
#pragma unroll
            for (int hl = 0; hl < 2; hl++)
#pragma unroll
                for (int p = 0; p < 4; p++) {
                    int row = wn * 64 + p * 16 + (lane & 7) + (lane >> 4) * 8;
                    int ch  = kk * 2 + ((lane >> 3) & 1);
                    int sw  = ch ^ ((row >> 1) & 3);
                    uint32_t addr = sB[hl] + row * 64 + sw * 16;
                    LDMATRIX_X4(b[hl][p][0], b[hl][p][1], b[hl][p][2], b[hl][p][3], addr);
                }
            // TERM-MAJOR: all 16 accs touched per term -> reuse distance 16
#pragma unroll
            for (int term = 0; term < 3; term++) {
                const int ahl = (term == 2) ? 1 : 0;
                const int bhl = (term == 1) ? 1 : 0;
#pragma unroll
                for (int mf = 0; mf < 2; mf++)
#pragma unroll
                    for (int p = 0; p < 4; p++)
#pragma unroll
                        for (int h = 0; h < 2; h++) {
                            float* cc = acc[mf][p * 2 + h];
                            MMA16816(cc[0], cc[1], cc[2], cc[3],
                                     a[ahl][mf][0], a[ahl][mf][1],
                                     a[ahl][mf][2], a[ahl][mf][3],
                                     b[bhl][p][h * 2], b[bhl][p][h * 2 + 1]);
                        }
            }
        }

        // wait so stage c+1 is complete entering next iteration
        if (c + 3 < NSTAGE)      CP_WAIT(2);
        else if (c + 2 < NSTAGE) CP_WAIT(1);
        else if (c + 1 < NSTAGE) CP_WAIT(0);
        __syncthreads();
    }

    const int g = lane >> 2, t2 = (lane & 3) * 2;
#pragma unroll
    for (int mf = 0; mf < 2; mf++) {
        int row0 = bm * 128 + wm * 32 + mf * 16 + g;
#pragma unroll
        for (int nf = 0; nf < 8; nf++) {
            int col = bn * 128 + wn * 64 + nf * 8 + t2;
            float bx = bias[col], by = bias[col + 1];
            float v0 = acc[mf][nf][0] + bx, v1 = acc[mf][nf][1] + by;
            float v2 = acc[mf][nf][2] + bx, v3 = acc[mf][nf][3] + by;
            if (Ch) {
                __nv_bfloat162 h01 = __floats2bfloat162_rn(v0, v1);
                __nv_bfloat162 h23 = __floats2bfloat162_rn(v2, v3);
                __nv_bfloat162 l01 = __floats2bfloat162_rn(
                    v0 - __bfloat162float(h01.x), v1 - __bfloat162float(h01.y));
                __nv_bfloat162 l23 = __floats2bfloat162_rn(
                    v2 - __bfloat162float(h23.x), v3 - __bfloat162float(h23.y));
                *(__nv_bfloat162*)(Ch + (size_t)row0 * N + col)       = h01;
                *(__nv_bfloat162*)(Cl + (size_t)row0 * N + col)       = l01;
                *(__nv_bfloat162*)(Ch + (size_t)(row0 + 8) * N + col) = h23;
                *(__nv_bfloat162*)(Cl + (size_t)(row0 + 8) * N + col) = l23;
            } else {
                float2 f0; f0.x = v0; f0.y = v1;
                float2 f1; f1.x = v2; f1.y = v3;
                *(float2*)(C + (size_t)row0 * N + col)       = f0;
                *(float2*)(C + (size_t)(row0 + 8) * N + col) = f1;
            }
        }
    }
}

// ---------------------------------------------------------------------------
// Tensor-core flash attention (bf16 hi/lo compensated, causal).
// BM=128 (8 warps x m16), BN=64, D=64. grid = (S/128, NH, B), 256 threads.
// smem: Qh(16K) Ql(16K) | 2 stages x [Kh Kl Vh Vl](8K each) = 96 KB.
// Swizzle on 128B rows: chunk' = ch ^ (row & 7).
// MMA groups ordered term-outer (same-acc distance 2 instead of 1).
// ---------------------------------------------------------------------------
__global__ __launch_bounds__(256, 2)
void flash_mma_kernel(const __nv_bfloat16* __restrict__ qkvh,
                      const __nv_bfloat16* __restrict__ qkvl,
                      __nv_bfloat16* __restrict__ oh,
                      __nv_bfloat16* __restrict__ ol)
{
    extern __shared__ char smf[];
    const uint32_t sb = smem_u32(smf);
    const int tid = threadIdx.x, wid = tid >> 5, lane = tid & 31;
    const int qt = (int)gridDim.x - 1 - (int)blockIdx.x;  // heavy tiles first
    const int h = blockIdx.y, b = blockIdx.z;
    const int g = lane >> 2, t = lane & 3;

    const size_t rowbase = (size_t)b * S_LEN * QKV_N + (size_t)h * HD;

    // ---- Q tile (hi+lo): 128 rows x 8 chunks x 2
    for (int i = tid; i < 2048; i += 256) {
        int arr = i >> 10;
        int r   = (i >> 3) & 127;
        int ch  = i & 7;
        const __nv_bfloat16* src =
            (arr ? qkvl : qkvh) + rowbase + (size_t)(qt * 128 + r) * QKV_N + ch * 8;
        CP_ASYNC16(sb + arr * 16384 + r * 128 + ((ch ^ (r & 7)) << 4), src);
    }

    auto stage_kv = [&](int kt) {
        const int s = kt & 1;
        for (int i = tid; i < 2048; i += 256) {
            int sub = i >> 9;            // 0 Kh, 1 Kl, 2 Vh, 3 Vl
            int r   = (i >> 3) & 63;
            int ch  = i & 7;
            size_t go = rowbase + (size_t)(kt * 64 + r) * QKV_N + ch * 8
                      + ((sub >> 1) ? 2 * (size_t)EMB : (size_t)EMB);
            const __nv_bfloat16* gp = (sub & 1) ? qkvl + go : qkvh + go;
            CP_ASYNC16(sb + 32768 + s * 32768 + sub * 8192 + r * 128
                       + ((ch ^ (r & 7)) << 4), gp);
        }
        CP_COMMIT();
    };

    stage_kv(0);   // commits Q + stage0 together (group 0)

    float m_[2] = { -1e30f, -1e30f }, l_[2] = { 0.f, 0.f };
    float oacc[8][4];
#pragma unroll
    for (int i = 0; i < 8; i++)
#pragma unroll
        for (int j = 0; j < 4; j++) oacc[i][j] = 0.f;

    const int nkt  = 2 * qt + 2;
    const int wrow = qt * 128 + wid * 16;   // warp's first q row (global in seq)

    for (int kt = 0; kt < nkt; kt++) {
        if (kt + 1 < nkt) { stage_kv(kt + 1); CP_WAIT(1); }
        else              { CP_WAIT(0); }
        __syncthreads();

        const bool active = (kt * 64) <= (wrow + 15);
        if (active) {
            const uint32_t stK = sb + 32768 + (uint32_t)(kt & 1) * 32768;
            const uint32_t stV = stK + 16384;

            // ---- S = Q K^T (3-term compensated)
            float sacc[8][4];
#pragma unroll
            for (int i = 0; i < 8; i++)
#pragma unroll
                for (int j = 0; j < 4; j++) sacc[i][j] = 0.f;

#pragma unroll
            for (int kk = 0; kk < 4; kk++) {
                uint32_t aH[4], aL[4];
                {
                    int row = wid * 16 + (lane & 7) + ((lane >> 3) & 1) * 8;
                    int ch  = 2 * kk + (lane >> 4);
                    uint32_t ad = sb + row * 128 + ((ch ^ (row & 7)) << 4);
                    LDMATRIX_X4(aH[0], aH[1], aH[2], aH[3], ad);
                    LDMATRIX_X4(aL[0], aL[1], aL[2], aL[3], ad + 16384);
                }
#pragma unroll
                for (int p = 0; p < 4; p++) {
                    uint32_t bH[4], bL[4];
                    int row = p * 16 + (lane & 7) + (lane >> 4) * 8;
                    int ch  = 2 * kk + ((lane >> 3) & 1);
                    uint32_t bd = stK + row * 128 + ((ch ^ (row & 7)) << 4);
                    LDMATRIX_X4(bH[0], bH[1], bH[2], bH[3], bd);
                    LDMATRIX_X4(bL[0], bL[1], bL[2], bL[3], bd + 8192);
                    // term-outer: same-acc distance 2
#pragma unroll
                    for (int term = 0; term < 3; term++) {
                        const uint32_t* aa = (term == 2) ? aL : aH;
                        const uint32_t* bb = (term == 1) ? bL : bH;
#pragma unroll
                        for (int hh = 0; hh < 2; hh++) {
                            float* cc = sacc[2 * p + hh];
                            MMA16816(cc[0], cc[1], cc[2], cc[3],
                                     aa[0], aa[1], aa[2], aa[3],
                                     bb[2 * hh], bb[2 * hh + 1]);
                        }
                    }
                }
            }

            // ---- scale + causal mask
            const int r0g = wrow + g;
#pragma unroll
            for (int nf = 0; nf < 8; nf++) {
                int c0 = kt * 64 + nf * 8 + 2 * t;
#pragma unroll
                for (int e = 0; e < 2; e++) {
                    int col = c0 + e;
                    sacc[nf][e]     = (col <= r0g)     ? sacc[nf][e] * 0.125f     : -1e30f;
                    sacc[nf][2 + e] = (col <= r0g + 8) ? sacc[nf][2 + e] * 0.125f : -1e30f;
                }
            }

            // ---- online softmax (rows g, g+8 per thread; quad reduction)
#pragma unroll
            for (int hf = 0; hf < 2; hf++) {
                float mx = -1e30f;
#pragma unroll
                for (int nf = 0; nf < 8; nf++)
                    mx = fmaxf(mx, fmaxf(sacc[nf][2 * hf], sacc[nf][2 * hf + 1]));
                mx = fmaxf(mx, __shfl_xor_sync(0xffffffffu, mx, 1));
                mx = fmaxf(mx, __shfl_xor_sync(0xffffffffu, mx, 2));
                float mnew  = fmaxf(m_[hf], mx);
                float alpha = __expf(m_[hf] - mnew);
                float rsum = 0.f;
#pragma unroll
                for (int nf = 0; nf < 8; nf++) {
                    float e0 = __expf(sacc[nf][2 * hf] - mnew);
                    float e1 = __expf(sacc[nf][2 * hf + 1] - mnew);
                    sacc[nf][2 * hf] = e0; sacc[nf][2 * hf + 1] = e1;
                    rsum += e0 + e1;
                }
                rsum += __shfl_xor_sync(0xffffffffu, rsum, 1);
                rsum += __shfl_xor_sync(0xffffffffu, rsum, 2);
                l_[hf] = l_[hf] * alpha + rsum;
                m_[hf] = mnew;
#pragma unroll
                for (int nf = 0; nf < 8; nf++) {
                    oacc[nf][2 * hf]     *= alpha;
                    oacc[nf][2 * hf + 1] *= alpha;
                }
            }

            // ---- O += P V (P hi/lo from S-regs; V frags via ldmatrix.trans)
#pragma unroll
            for (int s16 = 0; s16 < 4; s16++) {
                uint32_t pH[4], pL[4];
                {
                    const int nfl = 2 * s16, nfh = 2 * s16 + 1;
                    __nv_bfloat162 h0 = __floats2bfloat162_rn(sacc[nfl][0], sacc[nfl][1]);
                    __nv_bfloat162 h1 = __floats2bfloat162_rn(sacc[nfl][2], sacc[nfl][3]);
                    __nv_bfloat162 h2 = __floats2bfloat162_rn(sacc[nfh][0], sacc[nfh][1]);
                    __nv_bfloat162 h3 = __floats2bfloat162_rn(sacc[nfh][2], sacc[nfh][3]);
                    pH[0] = bf2u(h0); pH[1] = bf2u(h1); pH[2] = bf2u(h2); pH[3] = bf2u(h3);
                    __nv_bfloat162 e0 = __floats2bfloat162_rn(
                        sacc[nfl][0] - __bfloat162float(h0.x), sacc[nfl][1] - __bfloat162float(h0.y));
                    __nv_bfloat162 e1 = __floats2bfloat162_rn(
                        sacc[nfl][2] - __bfloat162float(h1.x), sacc[nfl][3] - __bfloat162float(h1.y));
                    __nv_bfloat162 e2 = __floats2bfloat162_rn(
                        sacc[nfh][0] - __bfloat162float(h2.x), sacc[nfh][1] - __bfloat162float(h2.y));
                    __nv_bfloat162 e3 = __floats2bfloat162_rn(
                        sacc[nfh][2] - __bfloat162float(h3.x), sacc[nfh][3] - __bfloat162float(h3.y));
                    pL[0] = bf2u(e0); pL[1] = bf2u(e1); pL[2] = bf2u(e2); pL[3] = bf2u(e3);
                }
#pragma unroll
                for (int p = 0; p < 4; p++) {
                    uint32_t vH[4], vL[4];
                    int row = s16 * 16 + (lane & 7) + ((lane >> 3) & 1) * 8;
                    int ch  = 2 * p + (lane >> 4);
                    uint32_t vd = stV + row * 128 + ((ch ^ (row & 7)) << 4);
                    LDMATRIX_X4_T(vH[0], vH[1], vH[2], vH[3], vd);
                    LDMATRIX_X4_T(vL[0], vL[1], vL[2], vL[3], vd + 8192);
                    // term-outer: same-acc distance 2
#pragma unroll
                    for (int term = 0; term < 3; term++) {
                        const uint32_t* pp = (term == 2) ? pL : pH;
                        const uint32_t* vv = (term == 1) ? vL : vH;
#pragma unroll
                        for (int hh = 0; hh < 2; hh++) {
                            float* cc = oacc[2 * p + hh];
                            MMA16816(cc[0], cc[1], cc[2], cc[3],
                                     pp[0], pp[1], pp[2], pp[3],
                                     vv[2 * hh], vv[2 * hh + 1]);
                        }
                    }
                }
            }
        }
        __syncthreads();
    }

    // ---- epilogue: O / l -> bf16 hi/lo
    const float inv0 = 1.f / l_[0], inv1 = 1.f / l_[1];
    const int grow0 = qt * 128 + wid * 16 + g;
    const size_t obase = (size_t)b * S_LEN * EMB + (size_t)h * HD;
#pragma unroll
    for (int nf = 0; nf < 8; nf++) {
        int d = nf * 8 + 2 * t;
        float v0 = oacc[nf][0] * inv0, v1 = oacc[nf][1] * inv0;
        float v2 = oacc[nf][2] * inv1, v3 = oacc[nf][3] * inv1;
        __nv_bfloat162 h01 = __floats2bfloat162_rn(v0, v1);
        __nv_bfloat162 h23 = __floats2bfloat162_rn(v2, v3);
        __nv_bfloat162 l01 = __floats2bfloat162_rn(
            v0 - __bfloat162float(h01.x), v1 - __bfloat162float(h01.y));
        __nv_bfloat162 l23 = __floats2bfloat162_rn(
            v2 - __bfloat162float(h23.x), v3 - __bfloat162float(h23.y));
        *(__nv_bfloat162*)(oh + obase + (size_t)grow0 * EMB + d)       = h01;
        *(__nv_bfloat162*)(ol + obase + (size_t)grow0 * EMB + d)       = l01;
        *(__nv_bfloat162*)(oh + obase + (size_t)(grow0 + 8) * EMB + d) = h23;
        *(__nv_bfloat162*)(ol + obase + (size_t)(grow0 + 8) * EMB + d) = l23;
    }
}

// ---------------------------------------------------------------------------
// launch
// ---------------------------------------------------------------------------
extern "C" void kernel_launch(void* const* d_in, const int* in_sizes, int n_in,
                              void* d_out, int out_size)
{
    const float* x     = (const float*)d_in[0];
    const float* wqkv  = (const float*)d_in[1];
    const float* bqkv  = (const float*)d_in[2];
    const float* wproj = (const float*)d_in[3];
    const float* bproj = (const float*)d_in[4];
    float* out = (float*)d_out;

    __nv_bfloat16 *qkvh, *qkvl, *ath, *atl, *xh, *xl, *wqh, *wql, *wph, *wpl;
    cudaGetSymbolAddress((void**)&qkvh, g_qkvh);
    cudaGetSymbolAddress((void**)&qkvl, g_qkvl);
    cudaGetSymbolAddress((void**)&ath,  g_ath);
    cudaGetSymbolAddress((void**)&atl,  g_atl);
    cudaGetSymbolAddress((void**)&xh,   g_xh);
    cudaGetSymbolAddress((void**)&xl,   g_xl);
    cudaGetSymbolAddress((void**)&wqh,  g_wqh);
    cudaGetSymbolAddress((void**)&wql,  g_wql);
    cudaGetSymbolAddress((void**)&wph,  g_wph);
    cudaGetSymbolAddress((void**)&wpl,  g_wpl);

    const int gemm_smem  = NPIPE * STG_BYTES;       // 128 KB
    const int flash_smem = 32768 + 2 * 32768;       // 96 KB
    cudaFuncSetAttribute(gemm_mma_kernel,
                         cudaFuncAttributeMaxDynamicSharedMemorySize, gemm_smem);
    cudaFuncSetAttribute(flash_mma_kernel,
                         cudaFuncAttributeMaxDynamicSharedMemorySize, flash_smem);

    // 0) input + weight splits
    {
        int n4 = ROWS * EMB / 4;
        split_kernel<<<(n4 + 255) / 256, 256>>>(x, xh, xl, n4);
        dim3 wb(32, 8);
        wsplit_kernel<<<dim3(QKV_N / 32, EMB / 32), wb>>>(wqkv, wqh, wql, EMB, QKV_N);
        wsplit_kernel<<<dim3(EMB / 32, EMB / 32), wb>>>(wproj, wph, wpl, EMB, EMB);
    }

    // 1) QKV = X @ Wqkv + b -> bf16 hi/lo directly
    {
        dim3 grid(QKV_N / 128, ROWS / 128);
        gemm_mma_kernel<<<grid, 256, gemm_smem>>>(xh, xl, wqh, wql, bqkv,
                                                  nullptr, qkvh, qkvl, QKV_N);
    }

    // 2) tensor-core causal flash attention -> attn bf16 hi/lo
    {
        dim3 grid(S_LEN / 128, NH, BATCH);
        flash_mma_kernel<<<grid, 256, flash_smem>>>(qkvh, qkvl, ath, atl);
    }

    // 3) out = attn @ Wproj + b (fp32 out)
    {
        dim3 grid(EMB / 128, ROWS / 128);
        gemm_mma_kernel<<<grid, 256, gemm_smem>>>(ath, atl, wph, wpl, bproj,
                                                  out, nullptr, nullptr, EMB);
    }
}

// round 14
// speedup vs baseline: 1.0955x; 1.0955x over previous
#include <cuda_runtime.h>
#include <cuda_bf16.h>
#include <cstdint>

// Problem constants
#define BATCH 2
#define S_LEN 2048
#define EMB   1024
#define NH    16
#define HD    64
#define QKV_N (3 * EMB)        // 3072
#define ROWS  (BATCH * S_LEN)  // 4096
#define GK    EMB              // GEMM K = 1024 for both GEMMs

// ---------------------------------------------------------------------------
// Scratch (device globals — allocation-free)
// ---------------------------------------------------------------------------
__device__ __align__(256) __nv_bfloat16 g_qkvh[ (size_t)ROWS * QKV_N ]; // QKV hi
__device__ __align__(256) __nv_bfloat16 g_qkvl[ (size_t)ROWS * QKV_N ]; // QKV lo
__device__ __align__(256) __nv_bfloat16 g_ath [ (size_t)ROWS * EMB ];   // attn hi
__device__ __align__(256) __nv_bfloat16 g_atl [ (size_t)ROWS * EMB ];   // attn lo
__device__ __align__(256) __nv_bfloat16 g_xh  [ (size_t)ROWS * EMB ];
__device__ __align__(256) __nv_bfloat16 g_xl  [ (size_t)ROWS * EMB ];
// transposed weight splits: [N, K] K-major
__device__ __align__(256) __nv_bfloat16 g_wqh[ (size_t)QKV_N * EMB ];
__device__ __align__(256) __nv_bfloat16 g_wql[ (size_t)QKV_N * EMB ];
__device__ __align__(256) __nv_bfloat16 g_wph[ (size_t)EMB * EMB ];
__device__ __align__(256) __nv_bfloat16 g_wpl[ (size_t)EMB * EMB ];

// ---------------------------------------------------------------------------
// helpers (non-arch-gated PTX only: cp.async / ldmatrix / mma.sync)
// ---------------------------------------------------------------------------
__device__ __forceinline__ uint32_t smem_u32(const void* p) {
    uint32_t a;
    asm("{ .reg .u64 t; cvta.to.shared.u64 t, %1; cvt.u32.u64 %0, t; }"
        : "=r"(a) : "l"(p));
    return a;
}

#define CP_ASYNC16(dst, src) \
    asm volatile("cp.async.cg.shared.global [%0], [%1], 16;" :: "r"(dst), "l"(src))
#define CP_COMMIT() asm volatile("cp.async.commit_group;" ::: "memory")
#define CP_WAIT(n)  asm volatile("cp.async.wait_group %0;" :: "n"(n) : "memory")

#define LDMATRIX_X4(r0, r1, r2, r3, addr) \
    asm volatile("ldmatrix.sync.aligned.m8n8.x4.shared.b16 {%0,%1,%2,%3}, [%4];" \
                 : "=r"(r0), "=r"(r1), "=r"(r2), "=r"(r3) : "r"(addr))

#define LDMATRIX_X4_T(r0, r1, r2, r3, addr) \
    asm volatile("ldmatrix.sync.aligned.m8n8.x4.trans.shared.b16 {%0,%1,%2,%3}, [%4];" \
                 : "=r"(r0), "=r"(r1), "=r"(r2), "=r"(r3) : "r"(addr))

#define MMA16816(c0, c1, c2, c3, a0, a1, a2, a3, b0, b1)                        \
    asm volatile("mma.sync.aligned.m16n8k16.row.col.f32.bf16.bf16.f32 "         \
                 "{%0,%1,%2,%3}, {%4,%5,%6,%7}, {%8,%9}, {%0,%1,%2,%3};"        \
                 : "+f"(c0), "+f"(c1), "+f"(c2), "+f"(c3)                       \
                 : "r"(a0), "r"(a1), "r"(a2), "r"(a3), "r"(b0), "r"(b1))

__device__ __forceinline__ uint32_t bf2u(__nv_bfloat162 v) {
    return *reinterpret_cast<uint32_t*>(&v);
}

// ---------------------------------------------------------------------------
// fp32 -> bf16 hi/lo split (elementwise, float4 vectorized)
// ---------------------------------------------------------------------------
__global__ void split_kernel(const float* __restrict__ in,
                             __nv_bfloat16* __restrict__ hi,
                             __nv_bfloat16* __restrict__ lo, int n4)
{
    int i = blockIdx.x * blockDim.x + threadIdx.x;
    if (i >= n4) return;
    float4 v = ((const float4*)in)[i];
    __nv_bfloat16 h0 = __float2bfloat16(v.x);
    __nv_bfloat16 h1 = __float2bfloat16(v.y);
    __nv_bfloat16 h2 = __float2bfloat16(v.z);
    __nv_bfloat16 h3 = __float2bfloat16(v.w);
    __nv_bfloat16 l0 = __float2bfloat16(v.x - __bfloat162float(h0));
    __nv_bfloat16 l1 = __float2bfloat16(v.y - __bfloat162float(h1));
    __nv_bfloat16 l2 = __float2bfloat16(v.z - __bfloat162float(h2));
    __nv_bfloat16 l3 = __float2bfloat16(v.w - __bfloat162float(h3));
    __nv_bfloat162 ph0; ph0.x = h0; ph0.y = h1;
    __nv_bfloat162 ph1; ph1.x = h2; ph1.y = h3;
    __nv_bfloat162 pl0; pl0.x = l0; pl0.y = l1;
    __nv_bfloat162 pl1; pl1.x = l2; pl1.y = l3;
    ((__nv_bfloat162*)hi)[2 * i]     = ph0;
    ((__nv_bfloat162*)hi)[2 * i + 1] = ph1;
    ((__nv_bfloat162*)lo)[2 * i]     = pl0;
    ((__nv_bfloat162*)lo)[2 * i + 1] = pl1;
}

// ---------------------------------------------------------------------------
// Weight transpose + split: W[K,N] fp32 -> Th/Tl[N,K] bf16
// ---------------------------------------------------------------------------
__global__ void wsplit_kernel(const float* __restrict__ W,
                              __nv_bfloat16* __restrict__ Th,
                              __nv_bfloat16* __restrict__ Tl, int K, int N)
{
    __shared__ float t[32][33];
    int tx = threadIdx.x, ty = threadIdx.y;
    int n0 = blockIdx.x * 32, k0 = blockIdx.y * 32;
    for (int j = ty; j < 32; j += 8)
        t[j][tx] = W[(size_t)(k0 + j) * N + n0 + tx];
    __syncthreads();
    for (int j = ty; j < 32; j += 8) {
        float v = t[tx][j];
        __nv_bfloat16 h = __float2bfloat16(v);
        __nv_bfloat16 l = __float2bfloat16(v - __bfloat162float(h));
        size_t o = (size_t)(n0 + j) * K + k0 + tx;
        Th[o] = h;
        Tl[o] = l;
    }
}

// ---------------------------------------------------------------------------
// bf16x3 GEMM via mma.sync: C = A@Bt^T + bias.
// 3-stage cp.async pipeline (96 KB smem -> 2 CTAs/SM), one barrier per stage.
// MMA loop is TERM-MAJOR: same-accumulator reuse distance = 16.
// Epilogue: if Ch != null, write bf16 hi/lo split; else fp32 C.
// ---------------------------------------------------------------------------
#define BK 32
#define NSTAGE (GK / BK)   // 32
#define STG_BYTES 32768
#define NPIPE 3

__global__ __launch_bounds__(256, 2)
void gemm_mma_kernel(const __nv_bfloat16* __restrict__ Ah,
                     const __nv_bfloat16* __restrict__ Al,
                     const __nv_bfloat16* __restrict__ Bh,
                     const __nv_bfloat16* __restrict__ Bl,
                     const float* __restrict__ bias,
                     float* __restrict__ C,
                     __nv_bfloat16* __restrict__ Ch,
                     __nv_bfloat16* __restrict__ Cl, int N)
{
    extern __shared__ char smc[];
    const uint32_t sbase = smem_u32(smc);
    const int tid  = threadIdx.x;
    const int wid  = tid >> 5;
    const int lane = tid & 31;
    const int bn = blockIdx.x, bm = blockIdx.y;
    const int wm = wid >> 1;
    const int wn = wid & 1;

    const __nv_bfloat16* gT[4] = {
        Ah + (size_t)bm * 128 * GK, Al + (size_t)bm * 128 * GK,
        Bh + (size_t)bn * 128 * GK, Bl + (size_t)bn * 128 * GK };

    auto stage_load = [&](int c) {
        const int s = c % NPIPE;
        const int k0 = c * BK;
#pragma unroll
        for (int t = 0; t < 4; t++) {
            const __nv_bfloat16* g = gT[t];
            const uint32_t sb = sbase + s * STG_BYTES + t * 8192;
#pragma unroll
            for (int r2 = 0; r2 < 2; r2++) {
                int idx = tid + r2 * 256;
                int row = idx >> 2;
                int ch  = idx & 3;
                int sw  = ch ^ ((row >> 1) & 3);
                const char* src = (const char*)(g + (size_t)row * GK + k0) + ch * 16;
                CP_ASYNC16(sb + row * 64 + sw * 16, src);
            }
        }
        CP_COMMIT();
    };

    float acc[2][8][4];
#pragma unroll
    for (int i = 0; i < 2; i++)
#pragma unroll
        for (int j = 0; j < 8; j++)
#pragma unroll
            for (int q = 0; q < 4; q++) acc[i][j][q] = 0.f;

    // prologue: stages 0,1 in flight; wait for stage 0
    stage_load(0);
    stage_load(1);
    CP_WAIT(1);
    __syncthreads();

    for (int c = 0; c < NSTAGE; c++) {
        // issue load for stage c+2 (slot last read in iter c-1, barrier-protected)
        if (c + 2 < NSTAGE) stage_load(c + 2);

        const uint32_t st = sbase + (uint32_t)(c % NPIPE) * STG_BYTES;
        const uint32_t sA[2] = { st, st + 8192 };
        const uint32_t sB[2] = { st + 16384, st + 24576 };

#pragma unroll
        for (int kk = 0; kk < 2; kk++) {
            uint32_t a[2][2][4];
#pragma unroll
            for (int hl = 0; hl < 2; hl++)
#pragma unroll
                for (int mf = 0; mf < 2; mf++) {
                    int row = wm * 32 + mf * 16 + (lane & 7) + ((lane >> 3) & 1) * 8;
                    int ch  = kk * 2 + (lane >> 4);
                    int sw  = ch ^ ((row >> 1) & 3);
                    uint32_t addr = sA[hl] + row * 64 + sw * 16;
                    LDMATRIX_X4(a[hl][mf][0], a[hl][mf][1], a[hl][mf][2], a[hl][mf][3], addr);
                }
            uint32_t b[2][4][4];
#pragma unroll
            for (int hl = 0; hl < 2; hl++)
#pragma unroll
                for (int p = 0; p < 4; p++) {
                    int row = wn * 64 + p * 16 + (lane & 7) + (lane >> 4) * 8;
                    int ch  = kk * 2 + ((lane >> 3) & 1);
                    int sw  = ch ^ ((row >> 1) & 3);
                    uint32_t addr = sB[hl] + row * 64 + sw * 16;
                    LDMATRIX_X4(b[hl][p][0], b[hl][p][1], b[hl][p][2], b[hl][p][3], addr);
                }
            // TERM-MAJOR: all 16 accs touched per term -> reuse distance 16
#pragma unroll
            for (int term = 0; term < 3; term++) {
                const int ahl = (term == 2) ? 1 : 0;
                const int bhl = (term == 1) ? 1 : 0;
#pragma unroll
                for (int mf = 0; mf < 2; mf++)
#pragma unroll
                    for (int p = 0; p < 4; p++)
#pragma unroll
                        for (int h = 0; h < 2; h++) {
                            float* cc = acc[mf][p * 2 + h];
                            MMA16816(cc[0], cc[1], cc[2], cc[3],
                                     a[ahl][mf][0], a[ahl][mf][1],
                                     a[ahl][mf][2], a[ahl][mf][3],
                                     b[bhl][p][h * 2], b[bhl][p][h * 2 + 1]);
                        }
            }
        }

        // wait so stage c+1 is complete entering next iteration
        if (c + 2 < NSTAGE)      CP_WAIT(1);
        else if (c + 1 < NSTAGE) CP_WAIT(0);
        __syncthreads();
    }

    const int g = lane >> 2, t2 = (lane & 3) * 2;
#pragma unroll
    for (int mf = 0; mf < 2; mf++) {
        int row0 = bm * 128 + wm * 32 + mf * 16 + g;
#pragma unroll
        for (int nf = 0; nf < 8; nf++) {
            int col = bn * 128 + wn * 64 + nf * 8 + t2;
            float bx = bias[col], by = bias[col + 1];
            float v0 = acc[mf][nf][0] + bx, v1 = acc[mf][nf][1] + by;
            float v2 = acc[mf][nf][2] + bx, v3 = acc[mf][nf][3] + by;
            if (Ch) {
                __nv_bfloat162 h01 = __floats2bfloat162_rn(v0, v1);
                __nv_bfloat162 h23 = __floats2bfloat162_rn(v2, v3);
                __nv_bfloat162 l01 = __floats2bfloat162_rn(
                    v0 - __bfloat162float(h01.x), v1 - __bfloat162float(h01.y));
                __nv_bfloat162 l23 = __floats2bfloat162_rn(
                    v2 - __bfloat162float(h23.x), v3 - __bfloat162float(h23.y));
                *(__nv_bfloat162*)(Ch + (size_t)row0 * N + col)       = h01;
                *(__nv_bfloat162*)(Cl + (size_t)row0 * N + col)       = l01;
                *(__nv_bfloat162*)(Ch + (size_t)(row0 + 8) * N + col) = h23;
                *(__nv_bfloat162*)(Cl + (size_t)(row0 + 8) * N + col) = l23;
            } else {
                float2 f0; f0.x = v0; f0.y = v1;
                float2 f1; f1.x = v2; f1.y = v3;
                *(float2*)(C + (size_t)row0 * N + col)       = f0;
                *(float2*)(C + (size_t)(row0 + 8) * N + col) = f1;
            }
        }
    }
}

// ---------------------------------------------------------------------------
// Tensor-core flash attention (bf16 hi/lo compensated, causal).
// BM=128 (8 warps x m16), BN=64, D=64. grid = (S/128, NH, B), 256 threads.
// smem: Qh(16K) Ql(16K) | 2 stages x [Kh Kl Vh Vl](8K each) = 96 KB.
// Swizzle on 128B rows: chunk' = ch ^ (row & 7).
// MMA groups ordered term-outer (same-acc distance 2 instead of 1).
// ---------------------------------------------------------------------------
__global__ __launch_bounds__(256, 2)
void flash_mma_kernel(const __nv_bfloat16* __restrict__ qkvh,
                      const __nv_bfloat16* __restrict__ qkvl,
                      __nv_bfloat16* __restrict__ oh,
                      __nv_bfloat16* __restrict__ ol)
{
    extern __shared__ char smf[];
    const uint32_t sb = smem_u32(smf);
    const int tid = threadIdx.x, wid = tid >> 5, lane = tid & 31;
    const int qt = (int)gridDim.x - 1 - (int)blockIdx.x;  // heavy tiles first
    const int h = blockIdx.y, b = blockIdx.z;
    const int g = lane >> 2, t = lane & 3;

    const size_t rowbase = (size_t)b * S_LEN * QKV_N + (size_t)h * HD;

    // ---- Q tile (hi+lo): 128 rows x 8 chunks x 2
    for (int i = tid; i < 2048; i += 256) {
        int arr = i >> 10;
        int r   = (i >> 3) & 127;
        int ch  = i & 7;
        const __nv_bfloat16* src =
            (arr ? qkvl : qkvh) + rowbase + (size_t)(qt * 128 + r) * QKV_N + ch * 8;
        CP_ASYNC16(sb + arr * 16384 + r * 128 + ((ch ^ (r & 7)) << 4), src);
    }

    auto stage_kv = [&](int kt) {
        const int s = kt & 1;
        for (int i = tid; i < 2048; i += 256) {
            int sub = i >> 9;            // 0 Kh, 1 Kl, 2 Vh, 3 Vl
            int r   = (i >> 3) & 63;
            int ch  = i & 7;
            size_t go = rowbase + (size_t)(kt * 64 + r) * QKV_N + ch * 8
                      + ((sub >> 1) ? 2 * (size_t)EMB : (size_t)EMB);
            const __nv_bfloat16* gp = (sub & 1) ? qkvl + go : qkvh + go;
            CP_ASYNC16(sb + 32768 + s * 32768 + sub * 8192 + r * 128
                       + ((ch ^ (r & 7)) << 4), gp);
        }
        CP_COMMIT();
    };

    stage_kv(0);   // commits Q + stage0 together (group 0)

    float m_[2] = { -1e30f, -1e30f }, l_[2] = { 0.f, 0.f };
    float oacc[8][4];
#pragma unroll
    for (int i = 0; i < 8; i++)
#pragma unroll
        for (int j = 0; j < 4; j++) oacc[i][j] = 0.f;

    const int nkt  = 2 * qt + 2;
    const int wrow = qt * 128 + wid * 16;   // warp's first q row (global in seq)

    for (int kt = 0; kt < nkt; kt++) {
        if (kt + 1 < nkt) { stage_kv(kt + 1); CP_WAIT(1); }
        else              { CP_WAIT(0); }
        __syncthreads();

        const bool active = (kt * 64) <= (wrow + 15);
        if (active) {
            const uint32_t stK = sb + 32768 + (uint32_t)(kt & 1) * 32768;
            const uint32_t stV = stK + 16384;

            // ---- S = Q K^T (3-term compensated)
            float sacc[8][4];
#pragma unroll
            for (int i = 0; i < 8; i++)
#pragma unroll
                for (int j = 0; j < 4; j++) sacc[i][j] = 0.f;

#pragma unroll
            for (int kk = 0; kk < 4; kk++) {
                uint32_t aH[4], aL[4];
                {
                    int row = wid * 16 + (lane & 7) + ((lane >> 3) & 1) * 8;
                    int ch  = 2 * kk + (lane >> 4);
                    uint32_t ad = sb + row * 128 + ((ch ^ (row & 7)) << 4);
                    LDMATRIX_X4(aH[0], aH[1], aH[2], aH[3], ad);
                    LDMATRIX_X4(aL[0], aL[1], aL[2], aL[3], ad + 16384);
                }
#pragma unroll
                for (int p = 0; p < 4; p++) {
                    uint32_t bH[4], bL[4];
                    int row = p * 16 + (lane & 7) + (lane >> 4) * 8;
                    int ch  = 2 * kk + ((lane >> 3) & 1);
                    uint32_t bd = stK + row * 128 + ((ch ^ (row & 7)) << 4);
                    LDMATRIX_X4(bH[0], bH[1], bH[2], bH[3], bd);
                    LDMATRIX_X4(bL[0], bL[1], bL[2], bL[3], bd + 8192);
                    // term-outer: same-acc distance 2
#pragma unroll
                    for (int term = 0; term < 3; term++) {
                        const uint32_t* aa = (term == 2) ? aL : aH;
                        const uint32_t* bb = (term == 1) ? bL : bH;
#pragma unroll
                        for (int hh = 0; hh < 2; hh++) {
                            float* cc = sacc[2 * p + hh];
                            MMA16816(cc[0], cc[1], cc[2], cc[3],
                                     aa[0], aa[1], aa[2], aa[3],
                                     bb[2 * hh], bb[2 * hh + 1]);
                        }
                    }
                }
            }

            // ---- scale + causal mask
            const int r0g = wrow + g;
#pragma unroll
            for (int nf = 0; nf < 8; nf++) {
                int c0 = kt * 64 + nf * 8 + 2 * t;
#pragma unroll
                for (int e = 0; e < 2; e++) {
                    int col = c0 + e;
                    sacc[nf][e]     = (col <= r0g)     ? sacc[nf][e] * 0.125f     : -1e30f;
                    sacc[nf][2 + e] = (col <= r0g + 8) ? sacc[nf][2 + e] * 0.125f : -1e30f;
                }
            }

            // ---- online softmax (rows g, g+8 per thread; quad reduction)
#pragma unroll
            for (int hf = 0; hf < 2; hf++) {
                float mx = -1e30f;
#pragma unroll
                for (int nf = 0; nf < 8; nf++)
                    mx = fmaxf(mx, fmaxf(sacc[nf][2 * hf], sacc[nf][2 * hf + 1]));
                mx = fmaxf(mx, __shfl_xor_sync(0xffffffffu, mx, 1));
                mx = fmaxf(mx, __shfl_xor_sync(0xffffffffu, mx, 2));
                float mnew  = fmaxf(m_[hf], mx);
                float alpha = __expf(m_[hf] - mnew);
                float rsum = 0.f;
#pragma unroll
                for (int nf = 0; nf < 8; nf++) {
                    float e0 = __expf(sacc[nf][2 * hf] - mnew);
                    float e1 = __expf(sacc[nf][2 * hf + 1] - mnew);
                    sacc[nf][2 * hf] = e0; sacc[nf][2 * hf + 1] = e1;
                    rsum += e0 + e1;
                }
                rsum += __shfl_xor_sync(0xffffffffu, rsum, 1);
                rsum += __shfl_xor_sync(0xffffffffu, rsum, 2);
                l_[hf] = l_[hf] * alpha + rsum;
                m_[hf] = mnew;
#pragma unroll
                for (int nf = 0; nf < 8; nf++) {
                    oacc[nf][2 * hf]     *= alpha;
                    oacc[nf][2 * hf + 1] *= alpha;
                }
            }

            // ---- O += P V (P hi/lo from S-regs; V frags via ldmatrix.trans)
#pragma unroll
            for (int s16 = 0; s16 < 4; s16++) {
                uint32_t pH[4], pL[4];
                {
                    const int nfl = 2 * s16, nfh = 2 * s16 + 1;
                    __nv_bfloat162 h0 = __floats2bfloat162_rn(sacc[nfl][0], sacc[nfl][1]);
                    __nv_bfloat162 h1 = __floats2bfloat162_rn(sacc[nfl][2], sacc[nfl][3]);
                    __nv_bfloat162 h2 = __floats2bfloat162_rn(sacc[nfh][0], sacc[nfh][1]);
                    __nv_bfloat162 h3 = __floats2bfloat162_rn(sacc[nfh][2], sacc[nfh][3]);
                    pH[0] = bf2u(h0); pH[1] = bf2u(h1); pH[2] = bf2u(h2); pH[3] = bf2u(h3);
                    __nv_bfloat162 e0 = __floats2bfloat162_rn(
                        sacc[nfl][0] - __bfloat162float(h0.x), sacc[nfl][1] - __bfloat162float(h0.y));
                    __nv_bfloat162 e1 = __floats2bfloat162_rn(
                        sacc[nfl][2] - __bfloat162float(h1.x), sacc[nfl][3] - __bfloat162float(h1.y));
                    __nv_bfloat162 e2 = __floats2bfloat162_rn(
                        sacc[nfh][0] - __bfloat162float(h2.x), sacc[nfh][1] - __bfloat162float(h2.y));
                    __nv_bfloat162 e3 = __floats2bfloat162_rn(
                        sacc[nfh][2] - __bfloat162float(h3.x), sacc[nfh][3] - __bfloat162float(h3.y));
                    pL[0] = bf2u(e0); pL[1] = bf2u(e1); pL[2] = bf2u(e2); pL[3] = bf2u(e3);
                }
#pragma unroll
                for (int p = 0; p < 4; p++) {
                    uint32_t vH[4], vL[4];
                    int row = s16 * 16 + (lane & 7) + ((lane >> 3) & 1) * 8;
                    int ch  = 2 * p + (lane >> 4);
                    uint32_t vd = stV + row * 128 + ((ch ^ (row & 7)) << 4);
                    LDMATRIX_X4_T(vH[0], vH[1], vH[2], vH[3], vd);
                    LDMATRIX_X4_T(vL[0], vL[1], vL[2], vL[3], vd + 8192);
                    // term-outer: same-acc distance 2
#pragma unroll
                    for (int term = 0; term < 3; term++) {
                        const uint32_t* pp = (term == 2) ? pL : pH;
                        const uint32_t* vv = (term == 1) ? vL : vH;
#pragma unroll
                        for (int hh = 0; hh < 2; hh++) {
                            float* cc = oacc[2 * p + hh];
                            MMA16816(cc[0], cc[1], cc[2], cc[3],
                                     pp[0], pp[1], pp[2], pp[3],
                                     vv[2 * hh], vv[2 * hh + 1]);
                        }
                    }
                }
            }
        }
        __syncthreads();
    }

    // ---- epilogue: O / l -> bf16 hi/lo
    const float inv0 = 1.f / l_[0], inv1 = 1.f / l_[1];
    const int grow0 = qt * 128 + wid * 16 + g;
    const size_t obase = (size_t)b * S_LEN * EMB + (size_t)h * HD;
#pragma unroll
    for (int nf = 0; nf < 8; nf++) {
        int d = nf * 8 + 2 * t;
        float v0 = oacc[nf][0] * inv0, v1 = oacc[nf][1] * inv0;
        float v2 = oacc[nf][2] * inv1, v3 = oacc[nf][3] * inv1;
        __nv_bfloat162 h01 = __floats2bfloat162_rn(v0, v1);
        __nv_bfloat162 h23 = __floats2bfloat162_rn(v2, v3);
        __nv_bfloat162 l01 = __floats2bfloat162_rn(
            v0 - __bfloat162float(h01.x), v1 - __bfloat162float(h01.y));
        __nv_bfloat162 l23 = __floats2bfloat162_rn(
            v2 - __bfloat162float(h23.x), v3 - __bfloat162float(h23.y));
        *(__nv_bfloat162*)(oh + obase + (size_t)grow0 * EMB + d)       = h01;
        *(__nv_bfloat162*)(ol + obase + (size_t)grow0 * EMB + d)       = l01;
        *(__nv_bfloat162*)(oh + obase + (size_t)(grow0 + 8) * EMB + d) = h23;
        *(__nv_bfloat162*)(ol + obase + (size_t)(grow0 + 8) * EMB + d) = l23;
    }
}

// ---------------------------------------------------------------------------
// launch
// ---------------------------------------------------------------------------
extern "C" void kernel_launch(void* const* d_in, const int* in_sizes, int n_in,
                              void* d_out, int out_size)
{
    const float* x     = (const float*)d_in[0];
    const float* wqkv  = (const float*)d_in[1];
    const float* bqkv  = (const float*)d_in[2];
    const float* wproj = (const float*)d_in[3];
    const float* bproj = (const float*)d_in[4];
    float* out = (float*)d_out;

    __nv_bfloat16 *qkvh, *qkvl, *ath, *atl, *xh, *xl, *wqh, *wql, *wph, *wpl;
    cudaGetSymbolAddress((void**)&qkvh, g_qkvh);
    cudaGetSymbolAddress((void**)&qkvl, g_qkvl);
    cudaGetSymbolAddress((void**)&ath,  g_ath);
    cudaGetSymbolAddress((void**)&atl,  g_atl);
    cudaGetSymbolAddress((void**)&xh,   g_xh);
    cudaGetSymbolAddress((void**)&xl,   g_xl);
    cudaGetSymbolAddress((void**)&wqh,  g_wqh);
    cudaGetSymbolAddress((void**)&wql,  g_wql);
    cudaGetSymbolAddress((void**)&wph,  g_wph);
    cudaGetSymbolAddress((void**)&wpl,  g_wpl);

    const int gemm_smem  = NPIPE * STG_BYTES;       // 96 KB -> 2 CTAs/SM
    const int flash_smem = 32768 + 2 * 32768;       // 96 KB
    cudaFuncSetAttribute(gemm_mma_kernel,
                         cudaFuncAttributeMaxDynamicSharedMemorySize, gemm_smem);
    cudaFuncSetAttribute(flash_mma_kernel,
                         cudaFuncAttributeMaxDynamicSharedMemorySize, flash_smem);

    // 0) input + weight splits
    {
        int n4 = ROWS * EMB / 4;
        split_kernel<<<(n4 + 255) / 256, 256>>>(x, xh, xl, n4);
        dim3 wb(32, 8);
        wsplit_kernel<<<dim3(QKV_N / 32, EMB / 32), wb>>>(wqkv, wqh, wql, EMB, QKV_N);
        wsplit_kernel<<<dim3(EMB / 32, EMB / 32), wb>>>(wproj, wph, wpl, EMB, EMB);
    }

    // 1) QKV = X @ Wqkv + b -> bf16 hi/lo directly
    {
        dim3 grid(QKV_N / 128, ROWS / 128);
        gemm_mma_kernel<<<grid, 256, gemm_smem>>>(xh, xl, wqh, wql, bqkv,
                                                  nullptr, qkvh, qkvl, QKV_N);
    }

    // 2) tensor-core causal flash attention -> attn bf16 hi/lo
    {
        dim3 grid(S_LEN / 128, NH, BATCH);
        flash_mma_kernel<<<grid, 256, flash_smem>>>(qkvh, qkvl, ath, atl);
    }

    // 3) out = attn @ Wproj + b (fp32 out)
    {
        dim3 grid(EMB / 128, ROWS / 128);
        gemm_mma_kernel<<<grid, 256, gemm_smem>>>(ath, atl, wph, wpl, bproj,
                                                  out, nullptr, nullptr, EMB);
    }
}